// round 4
// baseline (speedup 1.0000x reference)
#include <cuda_runtime.h>
#include <stdint.h>

// TrafficGCN: 2-layer GCN, N=100000, E=3200000, HIDDEN=16.
// R4: padded-CSR built in one pass (atomicAdd slot = degree count + bucket
// write), then PULL-based aggregation for both layers (warp per node,
// register accumulation + butterfly reduce). Removes all fp atomics and one
// full edge pass: 5 -> 4 random lane-ops per edge.
//
// Inputs: d_in[0]=x f32[N,3], d_in[1]=edge_index i32[2,E],
//         d_in[2]=W1 f32[3,16], d_in[3]=b1 f32[16], d_in[4]=W2 f32[16,1],
//         d_in[5]=b2 f32[1].  Output: f32[N].

#define MAXN 100608
#define HID 16
#define CAP 128          // slots per node; deg ~ Poisson(32), max ~70
#define OVF_CAP 65536

__device__ int    g_cnt[MAXN];            // in-degree (atomic slot counter)
__device__ int    g_csr[(size_t)MAXN * CAP];      // src lists, padded rows
__device__ int    g_ovf_cnt;
__device__ int2   g_ovf[OVF_CAP];         // (src,dst) overflow edges
__device__ float  g_isd[MAXN];
__device__ float4 g_px[MAXN];             // isd[i]*x[i] (w unused)
__device__ float  g_p[MAXN];              // isd[i]*g[i] layer-2 message

// ---------------------------------------------------------------------------
__global__ void k_zero(int n) {
    int i = blockIdx.x * blockDim.x + threadIdx.x;
    if (i < n) g_cnt[i] = 0;
    if (i == 0) g_ovf_cnt = 0;
}

__device__ __forceinline__ void build_one(int s, int d) {
    int slot = atomicAdd(&g_cnt[d], 1);
    if (slot < CAP) {
        g_csr[(size_t)d * CAP + slot] = s;
    } else {
        int o = atomicAdd(&g_ovf_cnt, 1);
        if (o < OVF_CAP) g_ovf[o] = make_int2(s, d);
    }
}

// Build CSR, 4 edges/thread
__global__ void k_build4(const int* __restrict__ src,
                         const int* __restrict__ dst, int E4) {
    int t = blockIdx.x * blockDim.x + threadIdx.x;
    if (t >= E4) return;
    int4 s = ((const int4*)src)[t];
    int4 d = ((const int4*)dst)[t];
    build_one(s.x, d.x);
    build_one(s.y, d.y);
    build_one(s.z, d.z);
    build_one(s.w, d.w);
}
__global__ void k_build1(const int* __restrict__ src,
                         const int* __restrict__ dst, int base, int E) {
    int e = base + blockIdx.x * blockDim.x + threadIdx.x;
    if (e < E) build_one(src[e], dst[e]);
}

// Per-node: isd = rsqrt(deg+1); px = isd * x
__global__ void k_node1(const float* __restrict__ x, int n) {
    int i = blockIdx.x * blockDim.x + threadIdx.x;
    if (i >= n) return;
    float isd = rsqrtf((float)(g_cnt[i] + 1));
    g_isd[i] = isd;
    g_px[i] = make_float4(isd * x[3*i+0], isd * x[3*i+1], isd * x[3*i+2], 0.f);
}

// Layer-1 pull + fused epilogue. Warp per node d:
//   sum = sum_{s in csr[d]} px[s] (+overflow) + px[d]
//   feat = isd[d]*sum; h = relu(feat@W1+b1); g = h@W2; p[d] = isd[d]*g
__global__ void k_pull1(const float* __restrict__ W1,
                        const float* __restrict__ b1,
                        const float* __restrict__ W2, int n) {
    int w = (blockIdx.x * blockDim.x + threadIdx.x) >> 5;
    if (w >= n) return;
    int lane = threadIdx.x & 31;
    int d = w;
    int m = min(g_cnt[d], CAP);
    const int* row = &g_csr[(size_t)d * CAP];

    float ax = 0.f, ay = 0.f, az = 0.f;
    for (int j = lane; j < m; j += 32) {
        int s = __ldg(&row[j]);
        float4 v = __ldg(&g_px[s]);
        ax += v.x; ay += v.y; az += v.z;
    }
    int ovn = g_ovf_cnt;
    if (ovn > 0) {
        for (int j = lane; j < ovn; j += 32) {
            int2 e = g_ovf[j];
            if (e.y == d) {
                float4 v = __ldg(&g_px[e.x]);
                ax += v.x; ay += v.y; az += v.z;
            }
        }
    }
#pragma unroll
    for (int o = 16; o; o >>= 1) {
        ax += __shfl_xor_sync(0xffffffffu, ax, o);
        ay += __shfl_xor_sync(0xffffffffu, ay, o);
        az += __shfl_xor_sync(0xffffffffu, az, o);
    }
    float isd = g_isd[d];
    float4 sp = __ldg(&g_px[d]);          // self-loop message
    float f0 = isd * (ax + sp.x);
    float f1 = isd * (ay + sp.y);
    float f2 = isd * (az + sp.z);

    // lanes 0..31 compute hidden unit c = lane&15 (each unit twice)
    int c = lane & 15;
    float h = f0 * __ldg(&W1[c]) + f1 * __ldg(&W1[HID + c])
            + f2 * __ldg(&W1[2 * HID + c]) + __ldg(&b1[c]);
    float ps = fmaxf(h, 0.f) * __ldg(&W2[c]);
#pragma unroll
    for (int o = 16; o; o >>= 1) ps += __shfl_xor_sync(0xffffffffu, ps, o);
    // ps = 2*g (each unit counted twice)
    if (lane == 0) g_p[d] = isd * 0.5f * ps;
}

// Layer-2 pull + final: out[d] = b2 + isd[d]*(sum p[s] (+ovf) + p[d])
__global__ void k_pull2(const float* __restrict__ b2,
                        float* __restrict__ out, int n) {
    int w = (blockIdx.x * blockDim.x + threadIdx.x) >> 5;
    if (w >= n) return;
    int lane = threadIdx.x & 31;
    int d = w;
    int m = min(g_cnt[d], CAP);
    const int* row = &g_csr[(size_t)d * CAP];

    float a = 0.f;
    for (int j = lane; j < m; j += 32) {
        a += __ldg(&g_p[__ldg(&row[j])]);
    }
    int ovn = g_ovf_cnt;
    if (ovn > 0) {
        for (int j = lane; j < ovn; j += 32) {
            int2 e = g_ovf[j];
            if (e.y == d) a += __ldg(&g_p[e.x]);
        }
    }
#pragma unroll
    for (int o = 16; o; o >>= 1) a += __shfl_xor_sync(0xffffffffu, a, o);
    if (lane == 0)
        out[d] = __ldg(&b2[0]) + g_isd[d] * (a + g_p[d]);
}

// ---------------------------------------------------------------------------
extern "C" void kernel_launch(void* const* d_in, const int* in_sizes, int n_in,
                              void* d_out, int out_size) {
    const float* x  = (const float*)d_in[0];
    const int*   ei = (const int*)  d_in[1];
    const float* W1 = (const float*)d_in[2];
    const float* b1 = (const float*)d_in[3];
    const float* W2 = (const float*)d_in[4];
    const float* b2 = (const float*)d_in[5];
    float* out = (float*)d_out;

    int n = in_sizes[0] / 3;
    int E = in_sizes[1] / 2;
    const int* src = ei;
    const int* dst = ei + E;

    const int T = 256;
    int nb_n = (n + T - 1) / T;

    int E4   = E / 4;
    int rem  = E - E4 * 4;
    int base = E4 * 4;
    int nb_e4 = (E4 + T - 1) / T;

    int warps_per_blk = T / 32;                       // 8
    int nb_w = (n + warps_per_blk - 1) / warps_per_blk;

    k_zero  <<<nb_n, T>>>(n);
    k_build4<<<nb_e4, T>>>(src, dst, E4);
    if (rem) k_build1<<<(rem + T - 1) / T, T>>>(src, dst, base, E);
    k_node1 <<<nb_n, T>>>(x, n);
    k_pull1 <<<nb_w, T>>>(W1, b1, W2, n);
    k_pull2 <<<nb_w, T>>>(b2, out, n);
}

// round 5
// speedup vs baseline: 1.1270x; 1.1270x over previous
#include <cuda_runtime.h>
#include <stdint.h>

// TrafficGCN: 2-layer GCN, N=100000, E=3200000, HIDDEN=16.
// R5: CSR build (one pass, atomic slot) + pull aggregation with 8-lanes-per-
// node groups (4 nodes/warp), weights hoisted to registers once per warp,
// 3-step group shuffle reduces. Targets the issue-bound overhead seen in R4.
//
// Inputs: d_in[0]=x f32[N,3], d_in[1]=edge_index i32[2,E],
//         d_in[2]=W1 f32[3,16], d_in[3]=b1 f32[16], d_in[4]=W2 f32[16,1],
//         d_in[5]=b2 f32[1].  Output: f32[N].

#define MAXN 100608
#define HID 16
#define CAP 96           // slots/node; deg ~ Poisson(32), overflow handled
#define OVF_CAP 65536

__device__ int    g_cnt[MAXN];
__device__ int    g_csr[(size_t)MAXN * CAP];
__device__ int    g_ovf_cnt;
__device__ int2   g_ovf[OVF_CAP];
__device__ float  g_isd[MAXN];
__device__ float4 g_px[MAXN];    // isd[i]*x[i] (w unused)
__device__ float  g_p[MAXN];     // isd[i]*g[i]

// ---------------------------------------------------------------------------
__global__ void k_zero(int n) {
    int i = blockIdx.x * blockDim.x + threadIdx.x;
    if (i < n) g_cnt[i] = 0;
    if (i == 0) g_ovf_cnt = 0;
}

__device__ __forceinline__ void build_one(int s, int d) {
    int slot = atomicAdd(&g_cnt[d], 1);
    if (slot < CAP) {
        g_csr[(size_t)d * CAP + slot] = s;
    } else {
        int o = atomicAdd(&g_ovf_cnt, 1);
        if (o < OVF_CAP) g_ovf[o] = make_int2(s, d);
    }
}

// Build CSR, 8 edges/thread
__global__ void k_build8(const int* __restrict__ src,
                         const int* __restrict__ dst, int E8) {
    int t = blockIdx.x * blockDim.x + threadIdx.x;
    if (t >= E8) return;
    int4 s0 = ((const int4*)src)[2 * t];
    int4 s1 = ((const int4*)src)[2 * t + 1];
    int4 d0 = ((const int4*)dst)[2 * t];
    int4 d1 = ((const int4*)dst)[2 * t + 1];
    build_one(s0.x, d0.x); build_one(s0.y, d0.y);
    build_one(s0.z, d0.z); build_one(s0.w, d0.w);
    build_one(s1.x, d1.x); build_one(s1.y, d1.y);
    build_one(s1.z, d1.z); build_one(s1.w, d1.w);
}
__global__ void k_build1(const int* __restrict__ src,
                         const int* __restrict__ dst, int base, int E) {
    int e = base + blockIdx.x * blockDim.x + threadIdx.x;
    if (e < E) build_one(src[e], dst[e]);
}

// Per-node: isd = rsqrt(deg+1); px = isd * x
__global__ void k_node1(const float* __restrict__ x, int n) {
    int i = blockIdx.x * blockDim.x + threadIdx.x;
    if (i >= n) return;
    float isd = rsqrtf((float)(g_cnt[i] + 1));
    g_isd[i] = isd;
    g_px[i] = make_float4(isd * x[3*i+0], isd * x[3*i+1], isd * x[3*i+2], 0.f);
}

// Layer-1 pull + fused MLP. 8 lanes per node, 4 nodes per warp.
// Lane j of a group owns hidden units c = j and c = j+8 (weights in regs).
__global__ void k_pull1(const float* __restrict__ W1,
                        const float* __restrict__ b1,
                        const float* __restrict__ W2, int n) {
    int gid  = blockIdx.x * blockDim.x + threadIdx.x;
    int lane = threadIdx.x & 31;
    int j    = lane & 7;                 // lane within group
    int d    = gid >> 3;                 // node id (8 lanes per node)
    // Hoisted per-lane weights (uniform across the 4 groups of the warp)
    int c0 = j, c1 = j + 8;
    float w00 = __ldg(&W1[c0]),          w01 = __ldg(&W1[c1]);
    float w10 = __ldg(&W1[HID + c0]),    w11 = __ldg(&W1[HID + c1]);
    float w20 = __ldg(&W1[2*HID + c0]),  w21 = __ldg(&W1[2*HID + c1]);
    float bb0 = __ldg(&b1[c0]),          bb1 = __ldg(&b1[c1]);
    float v20 = __ldg(&W2[c0]),          v21 = __ldg(&W2[c1]);

    if (d >= n) return;
    int m = min(g_cnt[d], CAP);
    const int* row = &g_csr[(size_t)d * CAP];

    float ax, ay, az;
    if (j == 0) { float4 sv = __ldg(&g_px[d]); ax = sv.x; ay = sv.y; az = sv.z; }
    else        { ax = 0.f; ay = 0.f; az = 0.f; }

    for (int t = j; t < m; t += 8) {
        float4 v = __ldg(&g_px[__ldg(&row[t])]);
        ax += v.x; ay += v.y; az += v.z;
    }
    int ovn = g_ovf_cnt;
    if (ovn > 0) {
        for (int t = j; t < ovn; t += 8) {
            int2 e = g_ovf[t];
            if (e.y == d) {
                float4 v = __ldg(&g_px[e.x]);
                ax += v.x; ay += v.y; az += v.z;
            }
        }
    }
#pragma unroll
    for (int o = 4; o; o >>= 1) {
        ax += __shfl_xor_sync(0xffffffffu, ax, o);
        ay += __shfl_xor_sync(0xffffffffu, ay, o);
        az += __shfl_xor_sync(0xffffffffu, az, o);
    }
    float isd = g_isd[d];
    float f0 = isd * ax, f1 = isd * ay, f2 = isd * az;

    float h0 = fmaxf(f0 * w00 + f1 * w10 + f2 * w20 + bb0, 0.f);
    float h1 = fmaxf(f0 * w01 + f1 * w11 + f2 * w21 + bb1, 0.f);
    float ps = h0 * v20 + h1 * v21;
#pragma unroll
    for (int o = 4; o; o >>= 1) ps += __shfl_xor_sync(0xffffffffu, ps, o);
    if (j == 0) g_p[d] = isd * ps;
}

// Layer-2 pull + final. 8 lanes per node.
__global__ void k_pull2(const float* __restrict__ b2,
                        float* __restrict__ out, int n) {
    int gid  = blockIdx.x * blockDim.x + threadIdx.x;
    int lane = threadIdx.x & 31;
    int j    = lane & 7;
    int d    = gid >> 3;
    if (d >= n) return;
    int m = min(g_cnt[d], CAP);
    const int* row = &g_csr[(size_t)d * CAP];

    float a = (j == 0) ? __ldg(&g_p[d]) : 0.f;   // self-loop
    for (int t = j; t < m; t += 8)
        a += __ldg(&g_p[__ldg(&row[t])]);
    int ovn = g_ovf_cnt;
    if (ovn > 0) {
        for (int t = j; t < ovn; t += 8) {
            int2 e = g_ovf[t];
            if (e.y == d) a += __ldg(&g_p[e.x]);
        }
    }
#pragma unroll
    for (int o = 4; o; o >>= 1) a += __shfl_xor_sync(0xffffffffu, a, o);
    if (j == 0) out[d] = __ldg(&b2[0]) + g_isd[d] * a;
}

// ---------------------------------------------------------------------------
extern "C" void kernel_launch(void* const* d_in, const int* in_sizes, int n_in,
                              void* d_out, int out_size) {
    const float* x  = (const float*)d_in[0];
    const int*   ei = (const int*)  d_in[1];
    const float* W1 = (const float*)d_in[2];
    const float* b1 = (const float*)d_in[3];
    const float* W2 = (const float*)d_in[4];
    const float* b2 = (const float*)d_in[5];
    float* out = (float*)d_out;

    int n = in_sizes[0] / 3;
    int E = in_sizes[1] / 2;
    const int* src = ei;
    const int* dst = ei + E;

    const int T = 256;
    int nb_n = (n + T - 1) / T;

    int E8   = E / 8;
    int rem  = E - E8 * 8;
    int base = E8 * 8;
    int nb_e8 = (E8 + T - 1) / T;

    // 8 lanes per node -> 8*n threads in pull kernels
    long long pull_threads = 8LL * n;
    int nb_p = (int)((pull_threads + T - 1) / T);

    k_zero  <<<nb_n, T>>>(n);
    k_build8<<<nb_e8, T>>>(src, dst, E8);
    if (rem) k_build1<<<(rem + T - 1) / T, T>>>(src, dst, base, E);
    k_node1 <<<nb_n, T>>>(x, n);
    k_pull1 <<<nb_p, T>>>(W1, b1, W2, n);
    k_pull2 <<<nb_p, T>>>(b2, out, n);
}

// round 6
// speedup vs baseline: 1.1602x; 1.0295x over previous
#include <cuda_runtime.h>
#include <stdint.h>

// TrafficGCN: 2-layer GCN, N=100000, E=3200000, HIDDEN=16.
// R6: CSR pull with int4-vectorized row reads + 4-wide predicated gathers
// per lane (MLP=4) to close the exposed-latency gap seen in R5
// (pull1: L2=40%, issue=21%, occ=65% -- nothing pegged).
//
// Inputs: d_in[0]=x f32[N,3], d_in[1]=edge_index i32[2,E],
//         d_in[2]=W1 f32[3,16], d_in[3]=b1 f32[16], d_in[4]=W2 f32[16,1],
//         d_in[5]=b2 f32[1].  Output: f32[N].

#define MAXN 100608
#define HID 16
#define CAP 96           // slots/node (16B-aligned rows); Poisson(32) max ~70
#define OVF_CAP 65536

__device__ int    g_cnt[MAXN];
__device__ int    g_csr[(size_t)MAXN * CAP];
__device__ int    g_ovf_cnt;
__device__ int2   g_ovf[OVF_CAP];
__device__ float  g_isd[MAXN];
__device__ float4 g_px[MAXN];    // isd[i]*x[i] (w unused)
__device__ float  g_p[MAXN];     // isd[i]*g[i]

// ---------------------------------------------------------------------------
__global__ void k_zero(int n) {
    int i = blockIdx.x * blockDim.x + threadIdx.x;
    if (i < n) g_cnt[i] = 0;
    if (i == 0) g_ovf_cnt = 0;
}

__device__ __forceinline__ void build_one(int s, int d) {
    int slot = atomicAdd(&g_cnt[d], 1);
    if (slot < CAP) {
        g_csr[(size_t)d * CAP + slot] = s;
    } else {
        int o = atomicAdd(&g_ovf_cnt, 1);
        if (o < OVF_CAP) g_ovf[o] = make_int2(s, d);
    }
}

// Build CSR, 8 edges/thread
__global__ void k_build8(const int* __restrict__ src,
                         const int* __restrict__ dst, int E8) {
    int t = blockIdx.x * blockDim.x + threadIdx.x;
    if (t >= E8) return;
    int4 s0 = ((const int4*)src)[2 * t];
    int4 s1 = ((const int4*)src)[2 * t + 1];
    int4 d0 = ((const int4*)dst)[2 * t];
    int4 d1 = ((const int4*)dst)[2 * t + 1];
    build_one(s0.x, d0.x); build_one(s0.y, d0.y);
    build_one(s0.z, d0.z); build_one(s0.w, d0.w);
    build_one(s1.x, d1.x); build_one(s1.y, d1.y);
    build_one(s1.z, d1.z); build_one(s1.w, d1.w);
}
__global__ void k_build1(const int* __restrict__ src,
                         const int* __restrict__ dst, int base, int E) {
    int e = base + blockIdx.x * blockDim.x + threadIdx.x;
    if (e < E) build_one(src[e], dst[e]);
}

// Per-node: isd = rsqrt(deg+1); px = isd * x
__global__ void k_node1(const float* __restrict__ x, int n) {
    int i = blockIdx.x * blockDim.x + threadIdx.x;
    if (i >= n) return;
    float isd = rsqrtf((float)(g_cnt[i] + 1));
    g_isd[i] = isd;
    g_px[i] = make_float4(isd * x[3*i+0], isd * x[3*i+1], isd * x[3*i+2], 0.f);
}

// Layer-1 pull + fused MLP. 8 lanes/node, 4 nodes/warp.
// Row read as int4 (4 slots per lane per iter; 32 slots per group-iter),
// 4 independent predicated gathers per lane => MLP=4.
__global__ void k_pull1(const float* __restrict__ W1,
                        const float* __restrict__ b1,
                        const float* __restrict__ W2, int n) {
    int gid  = blockIdx.x * blockDim.x + threadIdx.x;
    int lane = threadIdx.x & 31;
    int j    = lane & 7;
    int d    = gid >> 3;
    unsigned gmask = 0xFFu << (lane & 24);   // this 8-lane group

    int c0 = j, c1 = j + 8;
    float w00 = __ldg(&W1[c0]),          w01 = __ldg(&W1[c1]);
    float w10 = __ldg(&W1[HID + c0]),    w11 = __ldg(&W1[HID + c1]);
    float w20 = __ldg(&W1[2*HID + c0]),  w21 = __ldg(&W1[2*HID + c1]);
    float bb0 = __ldg(&b1[c0]),          bb1 = __ldg(&b1[c1]);
    float v20 = __ldg(&W2[c0]),          v21 = __ldg(&W2[c1]);

    if (d >= n) return;
    int m = min(g_cnt[d], CAP);
    const int4* row4 = (const int4*)(g_csr + (size_t)d * CAP);

    float ax, ay, az;
    if (j == 0) { float4 sv = __ldg(&g_px[d]); ax = sv.x; ay = sv.y; az = sv.z; }
    else        { ax = 0.f; ay = 0.f; az = 0.f; }

    for (int base = 0; base < m; base += 32) {
        int sl = base + 4 * j;
        int4 idx = __ldg(&row4[(base >> 2) + j]);
        if (sl + 0 < m) { float4 v = __ldg(&g_px[idx.x]); ax += v.x; ay += v.y; az += v.z; }
        if (sl + 1 < m) { float4 v = __ldg(&g_px[idx.y]); ax += v.x; ay += v.y; az += v.z; }
        if (sl + 2 < m) { float4 v = __ldg(&g_px[idx.z]); ax += v.x; ay += v.y; az += v.z; }
        if (sl + 3 < m) { float4 v = __ldg(&g_px[idx.w]); ax += v.x; ay += v.y; az += v.z; }
    }
    int ovn = g_ovf_cnt;
    if (ovn > 0) {
        for (int t = j; t < ovn; t += 8) {
            int2 e = g_ovf[t];
            if (e.y == d) {
                float4 v = __ldg(&g_px[e.x]);
                ax += v.x; ay += v.y; az += v.z;
            }
        }
    }
#pragma unroll
    for (int o = 4; o; o >>= 1) {
        ax += __shfl_xor_sync(gmask, ax, o);
        ay += __shfl_xor_sync(gmask, ay, o);
        az += __shfl_xor_sync(gmask, az, o);
    }
    float isd = g_isd[d];
    float f0 = isd * ax, f1 = isd * ay, f2 = isd * az;

    float h0 = fmaxf(f0 * w00 + f1 * w10 + f2 * w20 + bb0, 0.f);
    float h1 = fmaxf(f0 * w01 + f1 * w11 + f2 * w21 + bb1, 0.f);
    float ps = h0 * v20 + h1 * v21;
#pragma unroll
    for (int o = 4; o; o >>= 1) ps += __shfl_xor_sync(gmask, ps, o);
    if (j == 0) g_p[d] = isd * ps;
}

// Layer-2 pull + final. Same vectorized structure, scalar gathers.
__global__ void k_pull2(const float* __restrict__ b2,
                        float* __restrict__ out, int n) {
    int gid  = blockIdx.x * blockDim.x + threadIdx.x;
    int lane = threadIdx.x & 31;
    int j    = lane & 7;
    int d    = gid >> 3;
    unsigned gmask = 0xFFu << (lane & 24);
    if (d >= n) return;
    int m = min(g_cnt[d], CAP);
    const int4* row4 = (const int4*)(g_csr + (size_t)d * CAP);

    float a = (j == 0) ? __ldg(&g_p[d]) : 0.f;   // self-loop
    for (int base = 0; base < m; base += 32) {
        int sl = base + 4 * j;
        int4 idx = __ldg(&row4[(base >> 2) + j]);
        if (sl + 0 < m) a += __ldg(&g_p[idx.x]);
        if (sl + 1 < m) a += __ldg(&g_p[idx.y]);
        if (sl + 2 < m) a += __ldg(&g_p[idx.z]);
        if (sl + 3 < m) a += __ldg(&g_p[idx.w]);
    }
    int ovn = g_ovf_cnt;
    if (ovn > 0) {
        for (int t = j; t < ovn; t += 8) {
            int2 e = g_ovf[t];
            if (e.y == d) a += __ldg(&g_p[e.x]);
        }
    }
#pragma unroll
    for (int o = 4; o; o >>= 1) a += __shfl_xor_sync(gmask, a, o);
    if (j == 0) out[d] = __ldg(&b2[0]) + g_isd[d] * a;
}

// ---------------------------------------------------------------------------
extern "C" void kernel_launch(void* const* d_in, const int* in_sizes, int n_in,
                              void* d_out, int out_size) {
    const float* x  = (const float*)d_in[0];
    const int*   ei = (const int*)  d_in[1];
    const float* W1 = (const float*)d_in[2];
    const float* b1 = (const float*)d_in[3];
    const float* W2 = (const float*)d_in[4];
    const float* b2 = (const float*)d_in[5];
    float* out = (float*)d_out;

    int n = in_sizes[0] / 3;
    int E = in_sizes[1] / 2;
    const int* src = ei;
    const int* dst = ei + E;

    const int T = 256;
    int nb_n = (n + T - 1) / T;

    int E8   = E / 8;
    int rem  = E - E8 * 8;
    int base = E8 * 8;
    int nb_e8 = (E8 + T - 1) / T;

    long long pull_threads = 8LL * n;
    int nb_p = (int)((pull_threads + T - 1) / T);

    k_zero  <<<nb_n, T>>>(n);
    k_build8<<<nb_e8, T>>>(src, dst, E8);
    if (rem) k_build1<<<(rem + T - 1) / T, T>>>(src, dst, base, E);
    k_node1 <<<nb_n, T>>>(x, n);
    k_pull1 <<<nb_p, T>>>(W1, b1, W2, n);
    k_pull2 <<<nb_p, T>>>(b2, out, n);
}